// round 15
// baseline (speedup 1.0000x reference)
#include <cuda_runtime.h>
#include <cuda_fp16.h>
#include <math.h>

#define BATCH 8
#define SEQ   8192
#define DIM   512
#define HEADS 8
#define DH    64
#define SL    32
#define MTOT  (BATCH * SEQ)
#define KV_SPLITS 64
#define QDIM  (HEADS * SL)        // 256

// ---------------- device scratch ----------------
__device__ __half  g_xmid[(size_t)MTOT * DIM];
__device__ __half  g_qh  [(size_t)MTOT * QDIM];
__device__ float   g_S1p [(size_t)KV_SPLITS * 64 * SL * DH];
__device__ float   g_S0p [(size_t)KV_SPLITS * 64 * SL];
__device__ __half  g_Wp  [(size_t)DIM * DIM];           // W_in, k-paired fp16
__device__ __half  g_Zp  [(size_t)BATCH * QDIM * DIM];  // Z, k-paired fp16
__device__ __half2 g_WC  [(size_t)32 * 128];            // [Wq|Wk|Wv] k-paired fp16

__device__ __forceinline__ void mma_f16(float* c, const unsigned* a, const unsigned* b) {
    asm volatile(
        "mma.sync.aligned.m16n8k16.row.col.f32.f16.f16.f32 "
        "{%0,%1,%2,%3}, {%4,%5,%6,%7}, {%8,%9}, {%0,%1,%2,%3};"
        : "+f"(c[0]), "+f"(c[1]), "+f"(c[2]), "+f"(c[3])
        : "r"(a[0]), "r"(a[1]), "r"(a[2]), "r"(a[3]), "r"(b[0]), "r"(b[1]));
}
__device__ __forceinline__ unsigned smem_u32(const void* p) {
    return (unsigned)__cvta_generic_to_shared(p);
}
#define CP16(dst, src) asm volatile("cp.async.cg.shared.global [%0], [%1], 16;" :: "r"(dst), "l"(src))
#define CP_COMMIT()    asm volatile("cp.async.commit_group;")
#define CP_WAIT1()     asm volatile("cp.async.wait_group 1;")
#define CP_WAIT0()     asm volatile("cp.async.wait_group 0;")

__device__ __forceinline__ void sts_pack8(__half* dst, float4 a0, float4 a1) {
    uint4 u;
    __half2 h;
    h = __floats2half2_rn(a0.x, a0.y); u.x = *reinterpret_cast<unsigned*>(&h);
    h = __floats2half2_rn(a0.z, a0.w); u.y = *reinterpret_cast<unsigned*>(&h);
    h = __floats2half2_rn(a1.x, a1.y); u.z = *reinterpret_cast<unsigned*>(&h);
    h = __floats2half2_rn(a1.z, a1.w); u.w = *reinterpret_cast<unsigned*>(&h);
    *reinterpret_cast<uint4*>(dst) = u;
}

// ---------------- W -> k-paired fp16 layout ----------------
__global__ __launch_bounds__(256) void wpair_kernel(
    const float* __restrict__ W, __half* __restrict__ Wp, int K, int N)
{
    int idx = blockIdx.x * 256 + threadIdx.x;
    if (idx >= K * N) return;
    int k = idx / N, n = idx - k * N;
    Wp[((size_t)(k >> 1) * N + n) * 2 + (k & 1)] = __float2half(W[idx]);
}

// ---------------- [Wq|Wk|Wv] -> combined k-paired fp16 ----------------
__global__ __launch_bounds__(256) void wqkv_pair_kernel(
    const float* __restrict__ Wq, const float* __restrict__ Wk,
    const float* __restrict__ Wv, __half2* __restrict__ WC)
{
    int idx = blockIdx.x * 256 + threadIdx.x;
    if (idx >= 32 * 128) return;
    int kk = idx >> 7, c = idx & 127;
    float lo, hi;
    if (c < 32)      { lo = Wq[(2 * kk) * SL + c];        hi = Wq[(2 * kk + 1) * SL + c]; }
    else if (c < 64) { lo = Wk[(2 * kk) * SL + (c - 32)]; hi = Wk[(2 * kk + 1) * SL + (c - 32)]; }
    else             { lo = Wv[(2 * kk) * DH + (c - 64)]; hi = Wv[(2 * kk + 1) * DH + (c - 64)]; }
    WC[idx] = __floats2half2_rn(lo, hi);
}

// ---------------- FP16 GEMM, 2-stage (round-13 proven), A either fp32 (inline cvt) or fp16 ----
template<bool A32, bool HALF_OUT>
__global__ __launch_bounds__(256) void h16gemm_bias_kernel(
    const void* __restrict__ Av, const __half2* __restrict__ Bp,
    const float* __restrict__ bias, void* __restrict__ Cv, int K,
    size_t zStrideA, size_t zStrideB, size_t zStrideC)
{
    const int N = 512;
    __shared__ __half  As[2][128][24];
    __shared__ __half2 Bs[2][8][136];

    const int tid  = threadIdx.x;
    const int warp = tid >> 5;
    const int lane = tid & 31;
    const int g = lane >> 2;
    const int t = lane & 3;

    const int rowBase = blockIdx.y * 128;
    const int colBase = blockIdx.x * 128;
    const int wm = (warp & 3) * 32;
    const int wn = (warp >> 2) * 64;

    Bp += zStrideB * blockIdx.z;
    const size_t cBase = zStrideC * blockIdx.z;

    float acc[2][8][4];
#pragma unroll
    for (int mt = 0; mt < 2; mt++)
#pragma unroll
        for (int nt = 0; nt < 8; nt++)
#pragma unroll
            for (int i = 0; i < 4; i++) acc[mt][nt][i] = 0.f;

    const int aRow = tid >> 1;
    const int aCol8 = (tid & 1) * 8;
    const int bKK  = tid >> 5;
    const int bN4  = (tid & 31) * 4;

    const float*  Ag32 = A32 ? (const float*)Av + zStrideA * blockIdx.z
                               + (size_t)(rowBase + aRow) * K + aCol8 : nullptr;
    const __half* Ag16 = A32 ? nullptr : (const __half*)Av + zStrideA * blockIdx.z
                               + (size_t)(rowBase + aRow) * K + aCol8;
    const __half2* Bg = Bp + (size_t)bKK * N + colBase + bN4;

    unsigned sA = smem_u32(&As[0][aRow][aCol8]);
    unsigned sB = smem_u32(&Bs[0][bKK][bN4]);
    const unsigned strideA = 128 * 24 * 2;
    const unsigned strideB = 8 * 136 * 4;

    const int nIter = K >> 4;
    float4 a0, a1;

    // prologue: stage 0
    if (A32) {
        a0 = *reinterpret_cast<const float4*>(Ag32);
        a1 = *reinterpret_cast<const float4*>(Ag32 + 4);
        sts_pack8(&As[0][aRow][aCol8], a0, a1);
        CP16(sB, Bg);
        CP_COMMIT();
        if (nIter > 1) {
            a0 = *reinterpret_cast<const float4*>(Ag32 + 16);
            a1 = *reinterpret_cast<const float4*>(Ag32 + 20);
        }
    } else {
        CP16(sA, Ag16);
        CP16(sB, Bg);
        CP_COMMIT();
    }

#pragma unroll 1
    for (int it = 0; it < nIter; it++) {
        const int kt = it * 16;
        const int cur = it & 1;
        const int nb = cur ^ 1;
        if (it + 1 < nIter) {
            if (!A32) CP16(sA + nb * strideA, Ag16 + kt + 16);
            CP16(sB + nb * strideB, Bg + (size_t)(it + 1) * 8 * N);
            CP_COMMIT();
            CP_WAIT1();
        } else {
            CP_WAIT0();
        }
        __syncthreads();

        if (A32) {
            if (it + 1 < nIter) {
                sts_pack8(&As[nb][aRow][aCol8], a0, a1);
                if (it + 2 < nIter) {
                    a0 = *reinterpret_cast<const float4*>(Ag32 + (it + 2) * 16);
                    a1 = *reinterpret_cast<const float4*>(Ag32 + (it + 2) * 16 + 4);
                }
            }
        }

        unsigned af[2][4], bf[8][2];
#pragma unroll
        for (int mt = 0; mt < 2; mt++) {
            const int r0 = wm + mt * 16 + g;
            af[mt][0] = *reinterpret_cast<const unsigned*>(&As[cur][r0    ][2 * t    ]);
            af[mt][1] = *reinterpret_cast<const unsigned*>(&As[cur][r0 + 8][2 * t    ]);
            af[mt][2] = *reinterpret_cast<const unsigned*>(&As[cur][r0    ][2 * t + 8]);
            af[mt][3] = *reinterpret_cast<const unsigned*>(&As[cur][r0 + 8][2 * t + 8]);
        }
#pragma unroll
        for (int nt = 0; nt < 8; nt++) {
            const int c0 = wn + nt * 8 + g;
            bf[nt][0] = *reinterpret_cast<const unsigned*>(&Bs[cur][t    ][c0]);
            bf[nt][1] = *reinterpret_cast<const unsigned*>(&Bs[cur][t + 4][c0]);
        }
#pragma unroll
        for (int mt = 0; mt < 2; mt++)
#pragma unroll
            for (int nt = 0; nt < 8; nt++)
                mma_f16(acc[mt][nt], af[mt], bf[nt]);
        __syncthreads();   // protect buf cur + publish STS(nb)
    }

#pragma unroll
    for (int nt = 0; nt < 8; nt++) {
        const int col = colBase + wn + nt * 8 + 2 * t;
        const float bx = bias[col], by = bias[col + 1];
#pragma unroll
        for (int mt = 0; mt < 2; mt++) {
            const int row0 = rowBase + wm + mt * 16 + g;
            float2 o0, o1;
            o0.x = acc[mt][nt][0] + bx; o0.y = acc[mt][nt][1] + by;
            o1.x = acc[mt][nt][2] + bx; o1.y = acc[mt][nt][3] + by;
            if (HALF_OUT) {
                __half* C = reinterpret_cast<__half*>(Cv) + cBase;
                __half2 h0 = __floats2half2_rn(o0.x, o0.y);
                __half2 h1 = __floats2half2_rn(o1.x, o1.y);
                *reinterpret_cast<__half2*>(&C[(size_t)row0 * N + col])       = h0;
                *reinterpret_cast<__half2*>(&C[(size_t)(row0 + 8) * N + col]) = h1;
            } else {
                float* C = reinterpret_cast<float*>(Cv) + cBase;
                *reinterpret_cast<float2*>(&C[(size_t)row0 * N + col])       = o0;
                *reinterpret_cast<float2*>(&C[(size_t)(row0 + 8) * N + col]) = o1;
            }
        }
    }
}

// ---------------- Fused kv + q kernel (round-13 proven, unchanged) ----------------
__global__ __launch_bounds__(128) void kvq_fused_kernel(
    const __half* __restrict__ xmid, const __half2* __restrict__ WC)
{
    __shared__ __align__(16) char smA[17408];
    __shared__ __align__(16) __half Xs[64][72];
    __shared__ float Qs[64][36];

    __half*  Es   = reinterpret_cast<__half*>(smA);
    __half*  VspH = reinterpret_cast<__half*>(smA + 4608);
    const unsigned* WspW = reinterpret_cast<const unsigned*>(smA);
    const unsigned* VspW = reinterpret_cast<const unsigned*>(smA + 4608);

    const int split = blockIdx.x;
    const int h = blockIdx.y;
    const int b = blockIdx.z;
    const int bh = b * HEADS + h;
    const int tid = threadIdx.x;
    const int w = tid >> 5;
    const int lane = tid & 31;
    const int g = lane >> 2;
    const int t = lane & 3;

    const unsigned WspBase = smem_u32(smA);
    const unsigned XsBase  = smem_u32(Xs);

#pragma unroll
    for (int i = 0; i < 8; i++) {
        int idx = tid + i * 128;
        int row = idx >> 5, seg = idx & 31;
        CP16(WspBase + row * 544 + seg * 16, WC + row * 128 + seg * 4);
    }
    {
        const int n0 = split * 128;
#pragma unroll
        for (int i = 0; i < 4; i++) {
            int idx = tid + i * 128;
            int r = idx >> 3, c8 = (idx & 7) * 8;
            CP16(XsBase + r * 144 + c8 * 2,
                 xmid + (size_t)(b * SEQ + n0 + r) * DIM + h * DH + c8);
        }
    }
    CP_COMMIT();
    CP_WAIT0();
    __syncthreads();

    unsigned bfw[4][4][2];
#pragma unroll
    for (int nt = 0; nt < 4; nt++)
#pragma unroll
        for (int ks = 0; ks < 4; ks++) {
            const int c0 = 32 * w + nt * 8 + g;
            bfw[nt][ks][0] = WspW[(8 * ks + t    ) * 136 + c0];
            bfw[nt][ks][1] = WspW[(8 * ks + t + 4) * 136 + c0];
        }
    __syncthreads();

    float accS1[2][2][4];
#pragma unroll
    for (int mt = 0; mt < 2; mt++)
#pragma unroll
        for (int nt = 0; nt < 2; nt++)
#pragma unroll
            for (int i = 0; i < 4; i++) accS1[mt][nt][i] = 0.f;
    float s0acc = 0.f;

#pragma unroll 1
    for (int chunk = 0; chunk < 2; chunk++) {
        const int n0 = split * 128 + chunk * 64;

#pragma unroll
        for (int mt = 0; mt < 4; mt++) {
            float pacc[4][4];
#pragma unroll
            for (int nt = 0; nt < 4; nt++)
#pragma unroll
                for (int i = 0; i < 4; i++) pacc[nt][i] = 0.f;

#pragma unroll
            for (int ks = 0; ks < 4; ks++) {
                const int r0 = mt * 16 + g;
                unsigned af[4];
                af[0] = *reinterpret_cast<const unsigned*>(&Xs[r0    ][16 * ks + 2 * t    ]);
                af[1] = *reinterpret_cast<const unsigned*>(&Xs[r0 + 8][16 * ks + 2 * t    ]);
                af[2] = *reinterpret_cast<const unsigned*>(&Xs[r0    ][16 * ks + 2 * t + 8]);
                af[3] = *reinterpret_cast<const unsigned*>(&Xs[r0 + 8][16 * ks + 2 * t + 8]);
#pragma unroll
                for (int nt = 0; nt < 4; nt++)
                    mma_f16(pacc[nt], af, bfw[nt][ks]);
            }

#pragma unroll
            for (int nt = 0; nt < 4; nt++) {
                const int c0 = 32 * w + nt * 8 + 2 * t;
                const int r0 = mt * 16 + g;
                float v0 = pacc[nt][0], v1 = pacc[nt][1];
                float v2 = pacc[nt][2], v3 = pacc[nt][3];
                if (w == 0) {
                    Qs[r0    ][c0]     = v0;
                    Qs[r0    ][c0 + 1] = v1;
                    Qs[r0 + 8][c0]     = v2;
                    Qs[r0 + 8][c0 + 1] = v3;
                } else if (w == 1) {
                    const int s = c0 - 32;
                    Es[(s    ) * 72 + r0]     = __float2half(expf(v0));
                    Es[(s + 1) * 72 + r0]     = __float2half(expf(v1));
                    Es[(s    ) * 72 + r0 + 8] = __float2half(expf(v2));
                    Es[(s + 1) * 72 + r0 + 8] = __float2half(expf(v3));
                } else {
                    const int c = c0 - 64;
                    VspH[(r0 >> 1) * 144 + c * 2 + (r0 & 1)]                   = __float2half(v0);
                    VspH[(r0 >> 1) * 144 + (c + 1) * 2 + (r0 & 1)]             = __float2half(v1);
                    VspH[((r0 + 8) >> 1) * 144 + c * 2 + ((r0 + 8) & 1)]       = __float2half(v2);
                    VspH[((r0 + 8) >> 1) * 144 + (c + 1) * 2 + ((r0 + 8) & 1)] = __float2half(v3);
                }
            }
        }
        __syncthreads();

        if (chunk == 0) {
            const int n1 = split * 128 + 64;
#pragma unroll
            for (int i = 0; i < 4; i++) {
                int idx = tid + i * 128;
                int r = idx >> 3, c8 = (idx & 7) * 8;
                CP16(XsBase + r * 144 + c8 * 2,
                     xmid + (size_t)(b * SEQ + n1 + r) * DIM + h * DH + c8);
            }
            CP_COMMIT();
        }

        if (tid < 64) {
            float m = Qs[tid][0];
#pragma unroll
            for (int s = 1; s < 32; s++) m = fmaxf(m, Qs[tid][s]);
            float e[32], sum = 0.f;
#pragma unroll
            for (int s = 0; s < 32; s++) { e[s] = expf(Qs[tid][s] - m); sum += e[s]; }
            float inv = 1.f / sum;
#pragma unroll
            for (int s = 0; s < 32; s++) Qs[tid][s] = e[s] * inv;
        }
        if (tid >= 64 && tid < 96) {
            const int s = tid - 64;
            const __half2* Erow = reinterpret_cast<const __half2*>(&Es[s * 72]);
            float acc0 = 0.f;
#pragma unroll
            for (int r2 = 0; r2 < 32; r2++) {
                float2 f = __half22float2(Erow[r2]);
                acc0 += f.x + f.y;
            }
            s0acc += acc0;
        }
        __syncthreads();

        for (int idx = tid; idx < 64 * 8; idx += 128) {
            int r = idx >> 3, c4 = (idx & 7) * 4;
            float4 v = *reinterpret_cast<const float4*>(&Qs[r][c4]);
            __half2 h0 = __floats2half2_rn(v.x, v.y);
            __half2 h1 = __floats2half2_rn(v.z, v.w);
            uint2 o;
            o.x = *reinterpret_cast<unsigned*>(&h0);
            o.y = *reinterpret_cast<unsigned*>(&h1);
            *reinterpret_cast<uint2*>(
                &g_qh[(size_t)(b * SEQ + n0 + r) * QDIM + h * SL + c4]) = o;
        }

#pragma unroll
        for (int ks = 0; ks < 4; ks++) {
            unsigned af2[2][4];
#pragma unroll
            for (int mt = 0; mt < 2; mt++) {
                const int r0 = mt * 16 + g;
                af2[mt][0] = *reinterpret_cast<const unsigned*>(&Es[(r0    ) * 72 + 16 * ks + 2 * t    ]);
                af2[mt][1] = *reinterpret_cast<const unsigned*>(&Es[(r0 + 8) * 72 + 16 * ks + 2 * t    ]);
                af2[mt][2] = *reinterpret_cast<const unsigned*>(&Es[(r0    ) * 72 + 16 * ks + 2 * t + 8]);
                af2[mt][3] = *reinterpret_cast<const unsigned*>(&Es[(r0 + 8) * 72 + 16 * ks + 2 * t + 8]);
            }
#pragma unroll
            for (int nt = 0; nt < 2; nt++) {
                const int c0 = 16 * w + nt * 8 + g;
                unsigned bf2[2];
                bf2[0] = VspW[(8 * ks + t    ) * 72 + c0];
                bf2[1] = VspW[(8 * ks + t + 4) * 72 + c0];
#pragma unroll
                for (int mt = 0; mt < 2; mt++)
                    mma_f16(accS1[mt][nt], af2[mt], bf2);
            }
        }

        if (chunk == 0) { CP_WAIT0(); }
        __syncthreads();
    }

    float* base = g_S1p + ((size_t)split * 64 + bh) * (SL * DH);
#pragma unroll
    for (int mt = 0; mt < 2; mt++)
#pragma unroll
        for (int nt = 0; nt < 2; nt++) {
            const int s0 = mt * 16 + g;
            const int c  = 16 * w + nt * 8 + 2 * t;
            base[(s0    ) * DH + c]     = accS1[mt][nt][0];
            base[(s0    ) * DH + c + 1] = accS1[mt][nt][1];
            base[(s0 + 8) * DH + c]     = accS1[mt][nt][2];
            base[(s0 + 8) * DH + c + 1] = accS1[mt][nt][3];
        }
    if (tid >= 64 && tid < 96)
        g_S0p[((size_t)split * 64 + bh) * SL + (tid - 64)] = s0acc;
}

// ---------------- Merged kv-finalize + Z prep ----------------
// grid (HEADS, BATCH), 512 threads. Reduce S1p/S0p for bh (sp ascending, same order as before),
// kv in smem, then Z = kv @ W_out_h per 128-col block -> k-paired fp16 Zp.
__global__ __launch_bounds__(512) void kvz_kernel(const float* __restrict__ W_out)
{
    __shared__ float kvs[SL][DH];     // 8 KB
    __shared__ float s0s[SL];
    __shared__ float Wos[DH][128];    // 32 KB

    const int h = blockIdx.x;
    const int b = blockIdx.y;
    const int bh = b * HEADS + h;
    const int tid = threadIdx.x;

    // S0 reduction (threads 0..31), same sp order as old kv_final
    if (tid < SL) {
        float s0 = 0.f;
        for (int sp = 0; sp < KV_SPLITS; sp++)
            s0 += g_S0p[((size_t)sp * 64 + bh) * SL + tid];
        s0s[tid] = s0;
    }

    // S1 reduction: 2048 values, 4 per thread, coalesced per split
    float s1v[4] = {0.f, 0.f, 0.f, 0.f};
    for (int sp = 0; sp < KV_SPLITS; sp++) {
        const float* p = g_S1p + ((size_t)sp * 64 + bh) * (SL * DH);
#pragma unroll
        for (int j = 0; j < 4; j++) s1v[j] += p[tid + j * 512];
    }
    __syncthreads();
#pragma unroll
    for (int j = 0; j < 4; j++) {
        int i = tid + j * 512;
        reinterpret_cast<float*>(kvs)[i] = s1v[j] / s0s[i >> 6];
    }
    __syncthreads();

    // Z per 128-col block
#pragma unroll 1
    for (int cb = 0; cb < 4; cb++) {
        for (int i = tid; i < DH * 32; i += 512) {        // 2048 float4s
            int k = i >> 5, c4 = (i & 31) * 4;
            *reinterpret_cast<float4*>(&Wos[k][c4]) =
                *reinterpret_cast<const float4*>(
                    &W_out[(size_t)(h * DH + k) * DIM + cb * 128 + c4]);
        }
        __syncthreads();

        for (int i = tid; i < SL * 128; i += 512) {
            int s = i >> 7, c = i & 127;
            float d = 0.f;
#pragma unroll
            for (int k = 0; k < DH; k++) d = fmaf(kvs[s][k], Wos[k][c], d);
            const int kidx = h * SL + s;
            const int n    = cb * 128 + c;
            g_Zp[(size_t)b * QDIM * DIM + ((size_t)(kidx >> 1) * DIM + n) * 2 + (kidx & 1)]
                = __float2half(d);
        }
        __syncthreads();
    }
}

// ---------------- launch ----------------
extern "C" void kernel_launch(void* const* d_in, const int* in_sizes, int n_in,
                              void* d_out, int out_size)
{
    const float* x     = (const float*)d_in[0];
    const float* W_in  = (const float*)d_in[1];
    const float* b_in  = (const float*)d_in[2];
    const float* Wq    = (const float*)d_in[3];
    const float* Wk    = (const float*)d_in[4];
    const float* Wv    = (const float*)d_in[5];
    const float* W_out = (const float*)d_in[6];
    const float* b_out = (const float*)d_in[7];
    float* out = (float*)d_out;

    __half *xmid, *qh, *Wp, *Zp;
    __half2* WC;
    cudaGetSymbolAddress((void**)&xmid, g_xmid);
    cudaGetSymbolAddress((void**)&qh, g_qh);
    cudaGetSymbolAddress((void**)&Wp, g_Wp);
    cudaGetSymbolAddress((void**)&Zp, g_Zp);
    cudaGetSymbolAddress((void**)&WC, g_WC);

    // 0) weight conversions
    wpair_kernel<<<(DIM * DIM + 255) / 256, 256>>>(W_in, Wp, DIM, DIM);
    wqkv_pair_kernel<<<(32 * 128 + 255) / 256, 256>>>(Wq, Wk, Wv, WC);

    // 1) x_mid = x @ W_in + b_in   (fp32 A with inline cvt, fp16 output)
    dim3 g1(DIM / 128, MTOT / 128, 1);
    h16gemm_bias_kernel<true, true><<<g1, 256>>>(
        x, (const __half2*)Wp, b_in, xmid, DIM, 0, 0, 0);

    // 2) fused: q-softmax -> g_qh, kv split partials
    dim3 kvGrid(KV_SPLITS, HEADS, BATCH);
    kvq_fused_kernel<<<kvGrid, 128>>>(xmid, WC);

    // 3) merged kv finalize + Z prep
    dim3 zGrid(HEADS, BATCH);
    kvz_kernel<<<zGrid, 512>>>(W_out);

    // 4) out = Q @ Z_b + b_out   (fp16 A via cp.async, K=256, batched; fp32 output)
    dim3 g2(DIM / 128, SEQ / 128, BATCH);
    h16gemm_bias_kernel<false, false><<<g2, 256>>>(
        qh, (const __half2*)Zp, b_out, out, QDIM,
        (size_t)SEQ * QDIM,
        (size_t)QDIM * DIM / 2,
        (size_t)SEQ * DIM);
}

// round 16
// speedup vs baseline: 1.0150x; 1.0150x over previous
#include <cuda_runtime.h>
#include <cuda_fp16.h>
#include <math.h>

#define BATCH 8
#define SEQ   8192
#define DIM   512
#define HEADS 8
#define DH    64
#define SL    32
#define MTOT  (BATCH * SEQ)
#define KV_SPLITS 64
#define QDIM  (HEADS * SL)        // 256

// ---------------- device scratch ----------------
__device__ __half  g_xmid[(size_t)MTOT * DIM];
__device__ __half  g_xh  [(size_t)MTOT * DIM];
__device__ __half  g_qh  [(size_t)MTOT * QDIM];
__device__ float   g_S1p [(size_t)KV_SPLITS * 64 * SL * DH];
__device__ float   g_S0p [(size_t)KV_SPLITS * 64 * SL];
__device__ __half  g_Wp  [(size_t)DIM * DIM];           // W_in, k-paired fp16
__device__ __half  g_Zp  [(size_t)BATCH * QDIM * DIM];  // Z, k-paired fp16
__device__ __half2 g_WC  [(size_t)32 * 128];            // [Wq|Wk|Wv] k-paired fp16

__device__ __forceinline__ void mma_f16(float* c, const unsigned* a, const unsigned* b) {
    asm volatile(
        "mma.sync.aligned.m16n8k16.row.col.f32.f16.f16.f32 "
        "{%0,%1,%2,%3}, {%4,%5,%6,%7}, {%8,%9}, {%0,%1,%2,%3};"
        : "+f"(c[0]), "+f"(c[1]), "+f"(c[2]), "+f"(c[3])
        : "r"(a[0]), "r"(a[1]), "r"(a[2]), "r"(a[3]), "r"(b[0]), "r"(b[1]));
}
__device__ __forceinline__ unsigned smem_u32(const void* p) {
    return (unsigned)__cvta_generic_to_shared(p);
}
#define CP16(dst, src) asm volatile("cp.async.cg.shared.global [%0], [%1], 16;" :: "r"(dst), "l"(src))
#define CP_COMMIT()    asm volatile("cp.async.commit_group;")
#define CP_WAIT1()     asm volatile("cp.async.wait_group 1;")
#define CP_WAIT0()     asm volatile("cp.async.wait_group 0;")

// ---------------- fp32 -> fp16 bulk convert ----------------
__global__ __launch_bounds__(256) void f2h_kernel(
    const float4* __restrict__ in, uint2* __restrict__ out, int n4)
{
    int i = blockIdx.x * 256 + threadIdx.x;
    if (i >= n4) return;
    float4 v = in[i];
    __half2 h0 = __floats2half2_rn(v.x, v.y);
    __half2 h1 = __floats2half2_rn(v.z, v.w);
    uint2 o;
    o.x = *reinterpret_cast<unsigned*>(&h0);
    o.y = *reinterpret_cast<unsigned*>(&h1);
    out[i] = o;
}

// ---------------- W -> k-paired fp16 layout ----------------
__global__ __launch_bounds__(256) void wpair_kernel(
    const float* __restrict__ W, __half* __restrict__ Wp, int K, int N)
{
    int idx = blockIdx.x * 256 + threadIdx.x;
    if (idx >= K * N) return;
    int k = idx / N, n = idx - k * N;
    Wp[((size_t)(k >> 1) * N + n) * 2 + (k & 1)] = __float2half(W[idx]);
}

// ---------------- [Wq|Wk|Wv] -> combined k-paired fp16 ----------------
__global__ __launch_bounds__(256) void wqkv_pair_kernel(
    const float* __restrict__ Wq, const float* __restrict__ Wk,
    const float* __restrict__ Wv, __half2* __restrict__ WC)
{
    int idx = blockIdx.x * 256 + threadIdx.x;
    if (idx >= 32 * 128) return;
    int kk = idx >> 7, c = idx & 127;
    float lo, hi;
    if (c < 32)      { lo = Wq[(2 * kk) * SL + c];        hi = Wq[(2 * kk + 1) * SL + c]; }
    else if (c < 64) { lo = Wk[(2 * kk) * SL + (c - 32)]; hi = Wk[(2 * kk + 1) * SL + (c - 32)]; }
    else             { lo = Wv[(2 * kk) * DH + (c - 64)]; hi = Wv[(2 * kk + 1) * DH + (c - 64)]; }
    WC[idx] = __floats2half2_rn(lo, hi);
}

// ---------------- FP16 GEMM, 2-stage cp.async (round-13 proven form) ----------------
template<bool HALF_OUT>
__global__ __launch_bounds__(256) void h16gemm_bias_kernel(
    const __half* __restrict__ A, const __half2* __restrict__ Bp,
    const float* __restrict__ bias, void* __restrict__ Cv, int K,
    size_t zStrideA, size_t zStrideB, size_t zStrideC)
{
    const int N = 512;
    __shared__ __half  As[2][128][24];
    __shared__ __half2 Bs[2][8][136];

    const int tid  = threadIdx.x;
    const int warp = tid >> 5;
    const int lane = tid & 31;
    const int g = lane >> 2;
    const int t = lane & 3;

    const int rowBase = blockIdx.y * 128;
    const int colBase = blockIdx.x * 128;
    const int wm = (warp & 3) * 32;
    const int wn = (warp >> 2) * 64;

    A  += zStrideA * blockIdx.z;
    Bp += zStrideB * blockIdx.z;
    const size_t cBase = zStrideC * blockIdx.z;

    float acc[2][8][4];
#pragma unroll
    for (int mt = 0; mt < 2; mt++)
#pragma unroll
        for (int nt = 0; nt < 8; nt++)
#pragma unroll
            for (int i = 0; i < 4; i++) acc[mt][nt][i] = 0.f;

    const int aRow = tid >> 1;
    const int aOff = (tid & 1) * 8;
    const int bKK  = tid >> 5;
    const int bN4  = (tid & 31) * 4;

    const __half*  Ag = A + (size_t)(rowBase + aRow) * K + aOff;
    const __half2* Bg = Bp + (size_t)bKK * N + colBase + bN4;

    unsigned sA = smem_u32(&As[0][aRow][aOff]);
    unsigned sB = smem_u32(&Bs[0][bKK][bN4]);
    const unsigned strideA = 128 * 24 * 2;
    const unsigned strideB = 8 * 136 * 4;

    CP16(sA, Ag);
    CP16(sB, Bg);
    CP_COMMIT();

    const int nIter = K >> 4;
#pragma unroll 1
    for (int it = 0; it < nIter; it++) {
        const int kt = it * 16;
        const int cur = it & 1;
        if (it + 1 < nIter) {
            const unsigned offA = (cur ^ 1) ? strideA : 0;
            const unsigned offB = (cur ^ 1) ? strideB : 0;
            CP16(sA + offA, Ag + kt + 16);
            CP16(sB + offB, Bg + (size_t)(it + 1) * 8 * N);
            CP_COMMIT();
            CP_WAIT1();
        } else {
            CP_WAIT0();
        }
        __syncthreads();

        unsigned af[2][4], bf[8][2];
#pragma unroll
        for (int mt = 0; mt < 2; mt++) {
            const int r0 = wm + mt * 16 + g;
            af[mt][0] = *reinterpret_cast<const unsigned*>(&As[cur][r0    ][2 * t    ]);
            af[mt][1] = *reinterpret_cast<const unsigned*>(&As[cur][r0 + 8][2 * t    ]);
            af[mt][2] = *reinterpret_cast<const unsigned*>(&As[cur][r0    ][2 * t + 8]);
            af[mt][3] = *reinterpret_cast<const unsigned*>(&As[cur][r0 + 8][2 * t + 8]);
        }
#pragma unroll
        for (int nt = 0; nt < 8; nt++) {
            const int c0 = wn + nt * 8 + g;
            bf[nt][0] = *reinterpret_cast<const unsigned*>(&Bs[cur][t    ][c0]);
            bf[nt][1] = *reinterpret_cast<const unsigned*>(&Bs[cur][t + 4][c0]);
        }
#pragma unroll
        for (int mt = 0; mt < 2; mt++)
#pragma unroll
            for (int nt = 0; nt < 8; nt++)
                mma_f16(acc[mt][nt], af[mt], bf[nt]);
        __syncthreads();
    }

#pragma unroll
    for (int nt = 0; nt < 8; nt++) {
        const int col = colBase + wn + nt * 8 + 2 * t;
        const float bx = bias[col], by = bias[col + 1];
#pragma unroll
        for (int mt = 0; mt < 2; mt++) {
            const int row0 = rowBase + wm + mt * 16 + g;
            float2 o0, o1;
            o0.x = acc[mt][nt][0] + bx; o0.y = acc[mt][nt][1] + by;
            o1.x = acc[mt][nt][2] + bx; o1.y = acc[mt][nt][3] + by;
            if (HALF_OUT) {
                __half* C = reinterpret_cast<__half*>(Cv) + cBase;
                __half2 h0 = __floats2half2_rn(o0.x, o0.y);
                __half2 h1 = __floats2half2_rn(o1.x, o1.y);
                *reinterpret_cast<__half2*>(&C[(size_t)row0 * N + col])       = h0;
                *reinterpret_cast<__half2*>(&C[(size_t)(row0 + 8) * N + col]) = h1;
            } else {
                float* C = reinterpret_cast<float*>(Cv) + cBase;
                *reinterpret_cast<float2*>(&C[(size_t)row0 * N + col])       = o0;
                *reinterpret_cast<float2*>(&C[(size_t)(row0 + 8) * N + col]) = o1;
            }
        }
    }
}

// ---------------- Fused kv + q kernel (round-13 proven, unchanged) ----------------
__global__ __launch_bounds__(128) void kvq_fused_kernel(
    const __half* __restrict__ xmid, const __half2* __restrict__ WC)
{
    __shared__ __align__(16) char smA[17408];
    __shared__ __align__(16) __half Xs[64][72];
    __shared__ float Qs[64][36];

    __half*  Es   = reinterpret_cast<__half*>(smA);
    __half*  VspH = reinterpret_cast<__half*>(smA + 4608);
    const unsigned* WspW = reinterpret_cast<const unsigned*>(smA);
    const unsigned* VspW = reinterpret_cast<const unsigned*>(smA + 4608);

    const int split = blockIdx.x;
    const int h = blockIdx.y;
    const int b = blockIdx.z;
    const int bh = b * HEADS + h;
    const int tid = threadIdx.x;
    const int w = tid >> 5;
    const int lane = tid & 31;
    const int g = lane >> 2;
    const int t = lane & 3;

    const unsigned WspBase = smem_u32(smA);
    const unsigned XsBase  = smem_u32(Xs);

#pragma unroll
    for (int i = 0; i < 8; i++) {
        int idx = tid + i * 128;
        int row = idx >> 5, seg = idx & 31;
        CP16(WspBase + row * 544 + seg * 16, WC + row * 128 + seg * 4);
    }
    {
        const int n0 = split * 128;
#pragma unroll
        for (int i = 0; i < 4; i++) {
            int idx = tid + i * 128;
            int r = idx >> 3, c8 = (idx & 7) * 8;
            CP16(XsBase + r * 144 + c8 * 2,
                 xmid + (size_t)(b * SEQ + n0 + r) * DIM + h * DH + c8);
        }
    }
    CP_COMMIT();
    CP_WAIT0();
    __syncthreads();

    unsigned bfw[4][4][2];
#pragma unroll
    for (int nt = 0; nt < 4; nt++)
#pragma unroll
        for (int ks = 0; ks < 4; ks++) {
            const int c0 = 32 * w + nt * 8 + g;
            bfw[nt][ks][0] = WspW[(8 * ks + t    ) * 136 + c0];
            bfw[nt][ks][1] = WspW[(8 * ks + t + 4) * 136 + c0];
        }
    __syncthreads();

    float accS1[2][2][4];
#pragma unroll
    for (int mt = 0; mt < 2; mt++)
#pragma unroll
        for (int nt = 0; nt < 2; nt++)
#pragma unroll
            for (int i = 0; i < 4; i++) accS1[mt][nt][i] = 0.f;
    float s0acc = 0.f;

#pragma unroll 1
    for (int chunk = 0; chunk < 2; chunk++) {
        const int n0 = split * 128 + chunk * 64;

#pragma unroll
        for (int mt = 0; mt < 4; mt++) {
            float pacc[4][4];
#pragma unroll
            for (int nt = 0; nt < 4; nt++)
#pragma unroll
                for (int i = 0; i < 4; i++) pacc[nt][i] = 0.f;

#pragma unroll
            for (int ks = 0; ks < 4; ks++) {
                const int r0 = mt * 16 + g;
                unsigned af[4];
                af[0] = *reinterpret_cast<const unsigned*>(&Xs[r0    ][16 * ks + 2 * t    ]);
                af[1] = *reinterpret_cast<const unsigned*>(&Xs[r0 + 8][16 * ks + 2 * t    ]);
                af[2] = *reinterpret_cast<const unsigned*>(&Xs[r0    ][16 * ks + 2 * t + 8]);
                af[3] = *reinterpret_cast<const unsigned*>(&Xs[r0 + 8][16 * ks + 2 * t + 8]);
#pragma unroll
                for (int nt = 0; nt < 4; nt++)
                    mma_f16(pacc[nt], af, bfw[nt][ks]);
            }

#pragma unroll
            for (int nt = 0; nt < 4; nt++) {
                const int c0 = 32 * w + nt * 8 + 2 * t;
                const int r0 = mt * 16 + g;
                float v0 = pacc[nt][0], v1 = pacc[nt][1];
                float v2 = pacc[nt][2], v3 = pacc[nt][3];
                if (w == 0) {
                    Qs[r0    ][c0]     = v0;
                    Qs[r0    ][c0 + 1] = v1;
                    Qs[r0 + 8][c0]     = v2;
                    Qs[r0 + 8][c0 + 1] = v3;
                } else if (w == 1) {
                    const int s = c0 - 32;
                    Es[(s    ) * 72 + r0]     = __float2half(expf(v0));
                    Es[(s + 1) * 72 + r0]     = __float2half(expf(v1));
                    Es[(s    ) * 72 + r0 + 8] = __float2half(expf(v2));
                    Es[(s + 1) * 72 + r0 + 8] = __float2half(expf(v3));
                } else {
                    const int c = c0 - 64;
                    VspH[(r0 >> 1) * 144 + c * 2 + (r0 & 1)]                   = __float2half(v0);
                    VspH[(r0 >> 1) * 144 + (c + 1) * 2 + (r0 & 1)]             = __float2half(v1);
                    VspH[((r0 + 8) >> 1) * 144 + c * 2 + ((r0 + 8) & 1)]       = __float2half(v2);
                    VspH[((r0 + 8) >> 1) * 144 + (c + 1) * 2 + ((r0 + 8) & 1)] = __float2half(v3);
                }
            }
        }
        __syncthreads();

        if (chunk == 0) {
            const int n1 = split * 128 + 64;
#pragma unroll
            for (int i = 0; i < 4; i++) {
                int idx = tid + i * 128;
                int r = idx >> 3, c8 = (idx & 7) * 8;
                CP16(XsBase + r * 144 + c8 * 2,
                     xmid + (size_t)(b * SEQ + n1 + r) * DIM + h * DH + c8);
            }
            CP_COMMIT();
        }

        if (tid < 64) {
            float m = Qs[tid][0];
#pragma unroll
            for (int s = 1; s < 32; s++) m = fmaxf(m, Qs[tid][s]);
            float e[32], sum = 0.f;
#pragma unroll
            for (int s = 0; s < 32; s++) { e[s] = expf(Qs[tid][s] - m); sum += e[s]; }
            float inv = 1.f / sum;
#pragma unroll
            for (int s = 0; s < 32; s++) Qs[tid][s] = e[s] * inv;
        }
        if (tid >= 64 && tid < 96) {
            const int s = tid - 64;
            const __half2* Erow = reinterpret_cast<const __half2*>(&Es[s * 72]);
            float acc0 = 0.f;
#pragma unroll
            for (int r2 = 0; r2 < 32; r2++) {
                float2 f = __half22float2(Erow[r2]);
                acc0 += f.x + f.y;
            }
            s0acc += acc0;
        }
        __syncthreads();

        for (int idx = tid; idx < 64 * 8; idx += 128) {
            int r = idx >> 3, c4 = (idx & 7) * 4;
            float4 v = *reinterpret_cast<const float4*>(&Qs[r][c4]);
            __half2 h0 = __floats2half2_rn(v.x, v.y);
            __half2 h1 = __floats2half2_rn(v.z, v.w);
            uint2 o;
            o.x = *reinterpret_cast<unsigned*>(&h0);
            o.y = *reinterpret_cast<unsigned*>(&h1);
            *reinterpret_cast<uint2*>(
                &g_qh[(size_t)(b * SEQ + n0 + r) * QDIM + h * SL + c4]) = o;
        }

#pragma unroll
        for (int ks = 0; ks < 4; ks++) {
            unsigned af2[2][4];
#pragma unroll
            for (int mt = 0; mt < 2; mt++) {
                const int r0 = mt * 16 + g;
                af2[mt][0] = *reinterpret_cast<const unsigned*>(&Es[(r0    ) * 72 + 16 * ks + 2 * t    ]);
                af2[mt][1] = *reinterpret_cast<const unsigned*>(&Es[(r0 + 8) * 72 + 16 * ks + 2 * t    ]);
                af2[mt][2] = *reinterpret_cast<const unsigned*>(&Es[(r0    ) * 72 + 16 * ks + 2 * t + 8]);
                af2[mt][3] = *reinterpret_cast<const unsigned*>(&Es[(r0 + 8) * 72 + 16 * ks + 2 * t + 8]);
            }
#pragma unroll
            for (int nt = 0; nt < 2; nt++) {
                const int c0 = 16 * w + nt * 8 + g;
                unsigned bf2[2];
                bf2[0] = VspW[(8 * ks + t    ) * 72 + c0];
                bf2[1] = VspW[(8 * ks + t + 4) * 72 + c0];
#pragma unroll
                for (int mt = 0; mt < 2; mt++)
                    mma_f16(accS1[mt][nt], af2[mt], bf2);
            }
        }

        if (chunk == 0) { CP_WAIT0(); }
        __syncthreads();
    }

    float* base = g_S1p + ((size_t)split * 64 + bh) * (SL * DH);
#pragma unroll
    for (int mt = 0; mt < 2; mt++)
#pragma unroll
        for (int nt = 0; nt < 2; nt++) {
            const int s0 = mt * 16 + g;
            const int c  = 16 * w + nt * 8 + 2 * t;
            base[(s0    ) * DH + c]     = accS1[mt][nt][0];
            base[(s0    ) * DH + c + 1] = accS1[mt][nt][1];
            base[(s0 + 8) * DH + c]     = accS1[mt][nt][2];
            base[(s0 + 8) * DH + c + 1] = accS1[mt][nt][3];
        }
    if (tid >= 64 && tid < 96)
        g_S0p[((size_t)split * 64 + bh) * SL + (tid - 64)] = s0acc;
}

// ---------------- Merged kv-finalize + Z prep (round-15 validated) ----------------
__global__ __launch_bounds__(512) void kvz_kernel(const float* __restrict__ W_out)
{
    __shared__ float kvs[SL][DH];
    __shared__ float s0s[SL];
    __shared__ float Wos[DH][128];

    const int h = blockIdx.x;
    const int b = blockIdx.y;
    const int bh = b * HEADS + h;
    const int tid = threadIdx.x;

    if (tid < SL) {
        float s0 = 0.f;
        for (int sp = 0; sp < KV_SPLITS; sp++)
            s0 += g_S0p[((size_t)sp * 64 + bh) * SL + tid];
        s0s[tid] = s0;
    }

    float s1v[4] = {0.f, 0.f, 0.f, 0.f};
    for (int sp = 0; sp < KV_SPLITS; sp++) {
        const float* p = g_S1p + ((size_t)sp * 64 + bh) * (SL * DH);
#pragma unroll
        for (int j = 0; j < 4; j++) s1v[j] += p[tid + j * 512];
    }
    __syncthreads();
#pragma unroll
    for (int j = 0; j < 4; j++) {
        int i = tid + j * 512;
        reinterpret_cast<float*>(kvs)[i] = s1v[j] / s0s[i >> 6];
    }
    __syncthreads();

#pragma unroll 1
    for (int cb = 0; cb < 4; cb++) {
        for (int i = tid; i < DH * 32; i += 512) {
            int k = i >> 5, c4 = (i & 31) * 4;
            *reinterpret_cast<float4*>(&Wos[k][c4]) =
                *reinterpret_cast<const float4*>(
                    &W_out[(size_t)(h * DH + k) * DIM + cb * 128 + c4]);
        }
        __syncthreads();

        for (int i = tid; i < SL * 128; i += 512) {
            int s = i >> 7, c = i & 127;
            float d = 0.f;
#pragma unroll
            for (int k = 0; k < DH; k++) d = fmaf(kvs[s][k], Wos[k][c], d);
            const int kidx = h * SL + s;
            const int n    = cb * 128 + c;
            g_Zp[(size_t)b * QDIM * DIM + ((size_t)(kidx >> 1) * DIM + n) * 2 + (kidx & 1)]
                = __float2half(d);
        }
        __syncthreads();
    }
}

// ---------------- launch ----------------
extern "C" void kernel_launch(void* const* d_in, const int* in_sizes, int n_in,
                              void* d_out, int out_size)
{
    const float* x     = (const float*)d_in[0];
    const float* W_in  = (const float*)d_in[1];
    const float* b_in  = (const float*)d_in[2];
    const float* Wq    = (const float*)d_in[3];
    const float* Wk    = (const float*)d_in[4];
    const float* Wv    = (const float*)d_in[5];
    const float* W_out = (const float*)d_in[6];
    const float* b_out = (const float*)d_in[7];
    float* out = (float*)d_out;

    __half *xmid, *xh, *qh, *Wp, *Zp;
    __half2* WC;
    cudaGetSymbolAddress((void**)&xmid, g_xmid);
    cudaGetSymbolAddress((void**)&xh, g_xh);
    cudaGetSymbolAddress((void**)&qh, g_qh);
    cudaGetSymbolAddress((void**)&Wp, g_Wp);
    cudaGetSymbolAddress((void**)&Zp, g_Zp);
    cudaGetSymbolAddress((void**)&WC, g_WC);

    // 0) conversions
    const int n4 = MTOT * DIM / 4;
    f2h_kernel<<<(n4 + 255) / 256, 256>>>((const float4*)x, (uint2*)xh, n4);
    wpair_kernel<<<(DIM * DIM + 255) / 256, 256>>>(W_in, Wp, DIM, DIM);
    wqkv_pair_kernel<<<(32 * 128 + 255) / 256, 256>>>(Wq, Wk, Wv, WC);

    // 1) x_mid = x @ W_in + b_in   (fp16 mma, fp16 output)
    dim3 g1(DIM / 128, MTOT / 128, 1);
    h16gemm_bias_kernel<true><<<g1, 256>>>(xh, (const __half2*)Wp, b_in, xmid, DIM, 0, 0, 0);

    // 2) fused: q-softmax -> g_qh, kv split partials
    dim3 kvGrid(KV_SPLITS, HEADS, BATCH);
    kvq_fused_kernel<<<kvGrid, 128>>>(xmid, WC);

    // 3) merged kv finalize + Z prep
    dim3 zGrid(HEADS, BATCH);
    kvz_kernel<<<zGrid, 512>>>(W_out);

    // 4) out = Q @ Z_b + b_out   (fp16 mma, K=256, batched; fp32 output)
    dim3 g2(DIM / 128, SEQ / 128, BATCH);
    h16gemm_bias_kernel<false><<<g2, 256>>>(qh, (const __half2*)Zp, b_out, out, QDIM,
                                            (size_t)SEQ * QDIM,
                                            (size_t)QDIM * DIM / 2,
                                            (size_t)SEQ * DIM);
}